// round 7
// baseline (speedup 1.0000x reference)
#include <cuda_runtime.h>
#include <cuda_bf16.h>
#include <cstdint>

#define BB 8
#define HH 8
#define NN 16384
#define KSLOT 64
#define NSPLIT 16
#define CH 128
#define MLPR 4

__device__ __nv_bfloat16 g_hits[(size_t)BB * NN * 256];
__device__ __nv_bfloat16 g_Wkvt[1024 * 256];
__device__ __nv_bfloat16 g_q[(size_t)BB * HH * 64 * 64];
__device__ float g_pm[BB * HH * NSPLIT * 64];
__device__ float g_pl[BB * HH * NSPLIT * 64];
__device__ float g_po[(size_t)BB * HH * NSPLIT * 64 * 64];

struct __align__(16) FS {
    __nv_bfloat16 Hs[2][128 * 136];   // 2 x 34816 B  (k-half buffers)
    __nv_bfloat16 Ws[128 * 264];      // 67584 B (rows 0-63 Wk, 64-127 Wv)
    __nv_bfloat16 Ks[128 * 72];       // 18432 B
    __nv_bfloat16 Vs[128 * 72];       // 18432 B
    float mx[4][64];
    float smx[4][64];
};                                     // 176128 B

__device__ __forceinline__ uint32_t smaddr(const void* p) {
    return (uint32_t)__cvta_generic_to_shared(p);
}
__device__ __forceinline__ void ldsm4(uint32_t* r, const void* p) {
    uint32_t a = smaddr(p);
    asm volatile("ldmatrix.sync.aligned.m8n8.x4.shared.b16 {%0,%1,%2,%3},[%4];"
                 : "=r"(r[0]), "=r"(r[1]), "=r"(r[2]), "=r"(r[3]) : "r"(a));
}
__device__ __forceinline__ void ldsm4t(uint32_t* r, const void* p) {
    uint32_t a = smaddr(p);
    asm volatile("ldmatrix.sync.aligned.m8n8.x4.trans.shared.b16 {%0,%1,%2,%3},[%4];"
                 : "=r"(r[0]), "=r"(r[1]), "=r"(r[2]), "=r"(r[3]) : "r"(a));
}
__device__ __forceinline__ void mma16816(float* c, const uint32_t* a, uint32_t b0, uint32_t b1) {
    asm volatile("mma.sync.aligned.m16n8k16.row.col.f32.bf16.bf16.f32 "
                 "{%0,%1,%2,%3},{%4,%5,%6,%7},{%8,%9},{%0,%1,%2,%3};"
                 : "+f"(c[0]), "+f"(c[1]), "+f"(c[2]), "+f"(c[3])
                 : "r"(a[0]), "r"(a[1]), "r"(a[2]), "r"(a[3]), "r"(b0), "r"(b1));
}
__device__ __forceinline__ void cpasync16(void* dst, const void* src) {
    uint32_t d = smaddr(dst);
    asm volatile("cp.async.ca.shared.global [%0],[%1],16;" :: "r"(d), "l"(src) : "memory");
}
__device__ __forceinline__ void cpcommit() { asm volatile("cp.async.commit_group;" ::: "memory"); }
__device__ __forceinline__ void cpwaitN(int n) {
    if (n == 0)      asm volatile("cp.async.wait_group 0;" ::: "memory");
    else if (n == 1) asm volatile("cp.async.wait_group 1;" ::: "memory");
    else             asm volatile("cp.async.wait_group 2;" ::: "memory");
}
__device__ __forceinline__ uint32_t packbf(float a, float b) {
    __nv_bfloat162 t = __floats2bfloat162_rn(a, b);
    return *reinterpret_cast<uint32_t*>(&t);
}

__global__ void cvt_hits(const float4* __restrict__ in, int nvec) {
    __nv_bfloat162* out = reinterpret_cast<__nv_bfloat162*>(g_hits);
    for (int i = blockIdx.x * blockDim.x + threadIdx.x; i < nvec; i += gridDim.x * blockDim.x) {
        float4 v = in[i];
        out[2 * i]     = __floats2bfloat162_rn(v.x, v.y);
        out[2 * i + 1] = __floats2bfloat162_rn(v.z, v.w);
    }
}

__global__ void prep_w(const float* __restrict__ Wk, const float* __restrict__ Wv) {
    int i = blockIdx.x * blockDim.x + threadIdx.x;
    int j = i >> 8, kk = i & 255;
    float v = (j < 512) ? Wk[kk * 512 + j] : Wv[kk * 512 + (j - 512)];
    g_Wkvt[i] = __float2bfloat16(v);
}

__global__ void __launch_bounds__(256) ln1_q(const float* __restrict__ slots,
                                             const float* __restrict__ g1,
                                             const float* __restrict__ be1,
                                             const float* __restrict__ Wq) {
    __shared__ float xs[8][256];
    int t = threadIdx.x, lane = t & 31, w = t >> 5;
    int r0 = blockIdx.x * 8;
    {
        int row = r0 + w;
        float v[8];
        float sum = 0.f;
#pragma unroll
        for (int i = 0; i < 8; i++) { v[i] = slots[(size_t)row * 256 + lane + 32 * i]; sum += v[i]; }
#pragma unroll
        for (int off = 16; off; off >>= 1) sum += __shfl_xor_sync(0xffffffffu, sum, off);
        float mean = sum * (1.f / 256.f);
        float vs = 0.f;
#pragma unroll
        for (int i = 0; i < 8; i++) { float d = v[i] - mean; vs += d * d; }
#pragma unroll
        for (int off = 16; off; off >>= 1) vs += __shfl_xor_sync(0xffffffffu, vs, off);
        float inv = rsqrtf(vs * (1.f / 256.f) + 1e-5f);
#pragma unroll
        for (int i = 0; i < 8; i++) {
            int c = lane + 32 * i;
            xs[w][c] = (v[i] - mean) * inv * g1[c] + be1[c];
        }
    }
    __syncthreads();
    float acc0[8] = {}, acc1[8] = {};
    for (int kk = 0; kk < 256; kk++) {
        float w0 = Wq[kk * 512 + t];
        float w1 = Wq[kk * 512 + t + 256];
#pragma unroll
        for (int r = 0; r < 8; r++) {
            float x = xs[r][kk];
            acc0[r] += x * w0; acc1[r] += x * w1;
        }
    }
#pragma unroll
    for (int r = 0; r < 8; r++) {
        int row = r0 + r, b = row >> 6, k = row & 63;
        int h0 = t >> 6, d0 = t & 63;
        g_q[(((size_t)b * HH + h0) * 64 + k) * 64 + d0] = __float2bfloat16(acc0[r] * 0.125f);
        int j1 = t + 256, h1 = j1 >> 6, d1 = j1 & 63;
        g_q[(((size_t)b * HH + h1) * 64 + k) * 64 + d1] = __float2bfloat16(acc1[r] * 0.125f);
    }
}

// ---- fused KV projection + flash attention: 512 threads, 16 warps, flat ----
__global__ void __launch_bounds__(512, 1) fused_attn() {
    extern __shared__ char smraw[];
    FS& sm = *reinterpret_cast<FS*>(smraw);

    const int s = blockIdx.x, b = blockIdx.y;
    const int tid = threadIdx.x, lane = tid & 31, warp = tid >> 5;
    const int p = warp & 3, qd = warp >> 2;         // attention: m-group, n-quarter
    const int wm = p * 32, nq = qd;                 // projection: 32 rows, 32-col group of [K|V]
    const int g = lane >> 2, t4 = lane & 3;
    const size_t cta_row0 = (size_t)b * NN + (size_t)s * (NN / NSPLIT);

    auto issueH = [&](int c, int kh) {
        const __nv_bfloat16* src = g_hits + (cta_row0 + (size_t)c * CH) * 256 + kh * 128;
        __nv_bfloat16* dst = sm.Hs[kh];
#pragma unroll
        for (int i = 0; i < 4; i++) {
            int idx = tid + 512 * i;                // 0..2047
            int r = idx >> 4, cs = idx & 15;
            cpasync16(dst + r * 136 + cs * 8, src + (size_t)r * 256 + cs * 8);
        }
        cpcommit();
    };
    auto issueW = [&](int h) {
#pragma unroll
        for (int i = 0; i < 8; i++) {
            int idx = tid + 512 * i;                // 0..4095
            int j = idx >> 5, seg = idx & 31;
            int srow = (j < 64) ? h * 64 + j : 448 + h * 64 + j;
            cpasync16(sm.Ws + j * 264 + seg * 8, g_Wkvt + (size_t)srow * 256 + seg * 8);
        }
        cpcommit();
    };
    auto proj_half = [&](int kh, float acc[2][4][4]) {
        const __nv_bfloat16* Hb = sm.Hs[kh];
        const __nv_bfloat16* Wb = sm.Ws + nq * 32 * 264;
#pragma unroll
        for (int ks = 0; ks < 8; ks++) {
            uint32_t af[2][4], bf[2][4];
#pragma unroll
            for (int mi = 0; mi < 2; mi++)
                ldsm4(af[mi], Hb + (wm + mi * 16 + (lane & 15)) * 136 + ks * 16 + (lane >> 4) * 8);
#pragma unroll
            for (int nb = 0; nb < 2; nb++)
                ldsm4(bf[nb], Wb + (nb * 16 + (lane & 7) + ((lane >> 4) << 3)) * 264
                              + (kh * 8 + ks) * 16 + (lane & 8));
#pragma unroll
            for (int mi = 0; mi < 2; mi++)
#pragma unroll
                for (int nb = 0; nb < 2; nb++) {
                    mma16816(acc[mi][2 * nb],     af[mi], bf[nb][0], bf[nb][1]);
                    mma16816(acc[mi][2 * nb + 1], af[mi], bf[nb][2], bf[nb][3]);
                }
        }
    };

    issueW(0); issueH(0, 0); issueH(0, 1);

    float mrow[2], lrow[2], oacc[8][4];
    uint32_t qa[4][4];

    for (int h = 0; h < HH; h++) {
        const int bh = b * HH + h;
        {   // Q fragments direct from gmem; reset state
            const uint32_t* qp = (const uint32_t*)(g_q + (size_t)bh * 4096);
            int rq = p * 16 + g;
#pragma unroll
            for (int ks = 0; ks < 4; ks++) {
                int cb = ks * 16 + t4 * 2;
                qa[ks][0] = qp[(rq * 64 + cb) >> 1];
                qa[ks][1] = qp[((rq + 8) * 64 + cb) >> 1];
                qa[ks][2] = qp[(rq * 64 + cb + 8) >> 1];
                qa[ks][3] = qp[((rq + 8) * 64 + cb + 8) >> 1];
            }
            mrow[0] = mrow[1] = -1e30f;
            lrow[0] = lrow[1] = 0.f;
#pragma unroll
            for (int dt = 0; dt < 8; dt++)
#pragma unroll
                for (int r = 0; r < 4; r++) oacc[dt][r] = 0.f;
        }

        for (int c = 0; c < 8; c++) {
            float kacc[2][4][4] = {};
            cpwaitN(1); __syncthreads();
            proj_half(0, kacc);
            __syncthreads();
            if (c < 7) issueH(c + 1, 0);
            cpwaitN(c == 7 ? 0 : 1); __syncthreads();
            proj_half(1, kacc);
            __syncthreads();
            if (c < 7) issueH(c + 1, 1);
            else if (h < 7) { issueW(h + 1); issueH(0, 0); issueH(0, 1); }

            // epilogue: warp writes its 32x32 of K (nq<2) or V (nq>=2)
            {
                __nv_bfloat16* dst = (nq < 2) ? sm.Ks : sm.Vs;
                int cbase = (nq & 1) * 32;
#pragma unroll
                for (int mi = 0; mi < 2; mi++) {
                    int row = wm + mi * 16 + g;
#pragma unroll
                    for (int nj = 0; nj < 4; nj++) {
                        int col = cbase + nj * 8 + 2 * t4;
                        *(uint32_t*)&dst[row * 72 + col]       = packbf(kacc[mi][nj][0], kacc[mi][nj][1]);
                        *(uint32_t*)&dst[(row + 8) * 72 + col] = packbf(kacc[mi][nj][2], kacc[mi][nj][3]);
                    }
                }
            }
            __syncthreads();

            // attention: QK^T over this warp's 32-row n-quarter
            float sacc[4][4] = {};
#pragma unroll
            for (int ks = 0; ks < 4; ks++)
#pragma unroll
                for (int np = 0; np < 2; np++) {
                    uint32_t bf[4];
                    ldsm4(bf, sm.Ks + (qd * 32 + np * 16 + (lane & 7) + ((lane >> 4) << 3)) * 72
                               + ks * 16 + (lane & 8));
                    mma16816(sacc[2 * np],     qa[ks], bf[0], bf[1]);
                    mma16816(sacc[2 * np + 1], qa[ks], bf[2], bf[3]);
                }
            float mxv[2];
#pragma unroll
            for (int r = 0; r < 2; r++) {
                float m = -1e30f;
#pragma unroll
                for (int nt = 0; nt < 4; nt++)
                    m = fmaxf(m, fmaxf(sacc[nt][2 * r], sacc[nt][2 * r + 1]));
                m = fmaxf(m, __shfl_xor_sync(0xffffffffu, m, 1));
                m = fmaxf(m, __shfl_xor_sync(0xffffffffu, m, 2));
                mxv[r] = m;
            }
            if (t4 == 0) {
                sm.mx[qd][p * 16 + g]     = mxv[0];
                sm.mx[qd][p * 16 + g + 8] = mxv[1];
            }
            __syncthreads();
            float sc[2];
#pragma unroll
            for (int r = 0; r < 2; r++) {
                int row = p * 16 + g + r * 8;
                float mAll = fmaxf(fmaxf(sm.mx[0][row], sm.mx[1][row]),
                                   fmaxf(sm.mx[2][row], sm.mx[3][row]));
                float mnew = fmaxf(mrow[r], mAll);
                sc[r] = __expf(mrow[r] - mnew);
                mrow[r] = mnew;
                float sum = 0.f;
#pragma unroll
                for (int nt = 0; nt < 4; nt++) {
                    float p0 = __expf(sacc[nt][2 * r] - mnew);
                    float p1 = __expf(sacc[nt][2 * r + 1] - mnew);
                    sacc[nt][2 * r] = p0; sacc[nt][2 * r + 1] = p1;
                    sum += p0 + p1;
                }
                sum += __shfl_xor_sync(0xffffffffu, sum, 1);
                sum += __shfl_xor_sync(0xffffffffu, sum, 2);
                if (t4 == 0) sm.smx[qd][row] = sum;
            }
            __syncthreads();
#pragma unroll
            for (int r = 0; r < 2; r++) {
                int row = p * 16 + g + r * 8;
                lrow[r] = lrow[r] * sc[r] + sm.smx[0][row] + sm.smx[1][row]
                                          + sm.smx[2][row] + sm.smx[3][row];
#pragma unroll
                for (int dt = 0; dt < 8; dt++) {
                    oacc[dt][2 * r] *= sc[r]; oacc[dt][2 * r + 1] *= sc[r];
                }
            }
            uint32_t pf[2][4];
#pragma unroll
            for (int k2 = 0; k2 < 2; k2++) {
                pf[k2][0] = packbf(sacc[2 * k2][0],     sacc[2 * k2][1]);
                pf[k2][1] = packbf(sacc[2 * k2][2],     sacc[2 * k2][3]);
                pf[k2][2] = packbf(sacc[2 * k2 + 1][0], sacc[2 * k2 + 1][1]);
                pf[k2][3] = packbf(sacc[2 * k2 + 1][2], sacc[2 * k2 + 1][3]);
            }
#pragma unroll
            for (int k2 = 0; k2 < 2; k2++)
#pragma unroll
                for (int dp = 0; dp < 4; dp++) {
                    uint32_t vf[4];
                    ldsm4t(vf, sm.Vs + (qd * 32 + k2 * 16 + (lane & 15)) * 72
                                + dp * 16 + (lane >> 4) * 8);
                    mma16816(oacc[2 * dp],     pf[k2], vf[0], vf[1]);
                    mma16816(oacc[2 * dp + 1], pf[k2], vf[2], vf[3]);
                }

            if (c == 7) {   // merge 4 n-quarter partial O's through Ks scratch
                float* mg = (float*)sm.Ks;
                const int base = (bh * NSPLIT + s) * 64;
                const int r0 = p * 16 + g;
                __syncthreads();
#pragma unroll
                for (int q = 3; q >= 1; q--) {
                    if (qd == q) {
#pragma unroll
                        for (int dt = 0; dt < 8; dt++) {
                            int col = dt * 8 + 2 * t4;
                            if (q == 3) {
                                *(float2*)&mg[r0 * 64 + col]       = make_float2(oacc[dt][0], oacc[dt][1]);
                                *(float2*)&mg[(r0 + 8) * 64 + col] = make_float2(oacc[dt][2], oacc[dt][3]);
                            } else {
                                float2 a = *(float2*)&mg[r0 * 64 + col];
                                float2 bb = *(float2*)&mg[(r0 + 8) * 64 + col];
                                *(float2*)&mg[r0 * 64 + col]       = make_float2(a.x + oacc[dt][0], a.y + oacc[dt][1]);
                                *(float2*)&mg[(r0 + 8) * 64 + col] = make_float2(bb.x + oacc[dt][2], bb.y + oacc[dt][3]);
                            }
                        }
                    }
                    __syncthreads();
                }
                if (qd == 0) {
#pragma unroll
                    for (int dt = 0; dt < 8; dt++) {
                        int col = dt * 8 + 2 * t4;
                        float2 a = *(float2*)&mg[r0 * 64 + col];
                        float2 bb = *(float2*)&mg[(r0 + 8) * 64 + col];
                        *(float2*)&g_po[(size_t)(base + r0) * 64 + col] =
                            make_float2(a.x + oacc[dt][0], a.y + oacc[dt][1]);
                        *(float2*)&g_po[(size_t)(base + r0 + 8) * 64 + col] =
                            make_float2(bb.x + oacc[dt][2], bb.y + oacc[dt][3]);
                    }
                    if (t4 == 0) {
                        g_pm[base + r0] = mrow[0]; g_pm[base + r0 + 8] = mrow[1];
                        g_pl[base + r0] = lrow[0]; g_pl[base + r0 + 8] = lrow[1];
                    }
                }
                __syncthreads();
            }
        }
    }
}

// ---- combine splits + MLP + residual + LN2 ----
__global__ void __launch_bounds__(256) mlp_ln2(const float* __restrict__ slots,
                                               const float* __restrict__ W1,
                                               const float* __restrict__ b1,
                                               const float* __restrict__ W2,
                                               const float* __restrict__ b2,
                                               const float* __restrict__ g2,
                                               const float* __restrict__ be2,
                                               float* __restrict__ out) {
    __shared__ float av[MLPR][512];
    __shared__ float hid[MLPR][512];
    __shared__ float red[256];
    int t = threadIdx.x;
    int r0 = blockIdx.x * MLPR;
#pragma unroll
    for (int r = 0; r < MLPR; r++) {
        int row = r0 + r, bB = row >> 6, kk = row & 63;
#pragma unroll
        for (int jj = 0; jj < 2; jj++) {
            int d = t + 256 * jj;
            int h = d >> 6, dd = d & 63;
            int bh = bB * 8 + h;
            float M = -1e30f;
#pragma unroll
            for (int ss = 0; ss < NSPLIT; ss++)
                M = fmaxf(M, g_pm[(bh * NSPLIT + ss) * 64 + kk]);
            float L = 0.f, acc = 0.f;
#pragma unroll
            for (int ss = 0; ss < NSPLIT; ss++) {
                int idx = (bh * NSPLIT + ss) * 64 + kk;
                float w = __expf(g_pm[idx] - M);
                L   += g_pl[idx] * w;
                acc += g_po[(size_t)idx * 64 + dd] * w;
            }
            av[r][d] = acc / L;
        }
    }
    __syncthreads();
    float a0[MLPR], a1[MLPR];
    float bb0 = b1[t], bb1 = b1[t + 256];
#pragma unroll
    for (int r = 0; r < MLPR; r++) { a0[r] = bb0; a1[r] = bb1; }
    for (int kk = 0; kk < 512; kk++) {
        float w0 = W1[kk * 512 + t];
        float w1 = W1[kk * 512 + t + 256];
#pragma unroll
        for (int r = 0; r < MLPR; r++) {
            float x = av[r][kk];
            a0[r] += x * w0; a1[r] += x * w1;
        }
    }
#pragma unroll
    for (int r = 0; r < MLPR; r++) {
        hid[r][t] = fmaxf(a0[r], 0.f);
        hid[r][t + 256] = fmaxf(a1[r], 0.f);
    }
    __syncthreads();
    float o[MLPR];
    float c0 = b2[t];
#pragma unroll
    for (int r = 0; r < MLPR; r++) o[r] = c0;
    for (int kk = 0; kk < 512; kk++) {
        float w = W2[kk * 256 + t];
#pragma unroll
        for (int r = 0; r < MLPR; r++) o[r] += hid[r][kk] * w;
    }
    float gg = g2[t], bbn = be2[t];
    for (int r = 0; r < MLPR; r++) {
        float x = slots[(size_t)(r0 + r) * 256 + t] + o[r];
        red[t] = x; __syncthreads();
        for (int off = 128; off; off >>= 1) { if (t < off) red[t] += red[t + off]; __syncthreads(); }
        float mean = red[0] * (1.f / 256.f); __syncthreads();
        float d = x - mean;
        red[t] = d * d; __syncthreads();
        for (int off = 128; off; off >>= 1) { if (t < off) red[t] += red[t + off]; __syncthreads(); }
        float var = red[0] * (1.f / 256.f); __syncthreads();
        out[(size_t)(r0 + r) * 256 + t] = d * rsqrtf(var + 1e-5f) * gg + bbn;
    }
}

extern "C" void kernel_launch(void* const* d_in, const int* in_sizes, int n_in,
                              void* d_out, int out_size) {
    const float* slots = (const float*)d_in[0];
    const float* hits  = (const float*)d_in[1];
    const float* ln1g  = (const float*)d_in[2];
    const float* ln1b  = (const float*)d_in[3];
    const float* Wq    = (const float*)d_in[4];
    const float* Wk    = (const float*)d_in[5];
    const float* Wv    = (const float*)d_in[6];
    const float* W1    = (const float*)d_in[7];
    const float* b1    = (const float*)d_in[8];
    const float* W2    = (const float*)d_in[9];
    const float* b2    = (const float*)d_in[10];
    const float* ln2g  = (const float*)d_in[11];
    const float* ln2b  = (const float*)d_in[12];
    float* out = (float*)d_out;

    cudaFuncSetAttribute(fused_attn, cudaFuncAttributeMaxDynamicSharedMemorySize,
                         (int)sizeof(FS));
    int nvec = (BB * NN * 256) / 4;
    cvt_hits<<<8192, 256>>>((const float4*)hits, nvec);
    prep_w<<<1024, 256>>>(Wk, Wv);
    ln1_q<<<64, 256>>>(slots, ln1g, ln1b, Wq);
    fused_attn<<<dim3(NSPLIT, BB), 512, sizeof(FS)>>>();
    mlp_ln2<<<BB * KSLOT / MLPR, 256>>>(slots, W1, b1, W2, b2, ln2g, ln2b, out);
}

// round 8
// speedup vs baseline: 1.3098x; 1.3098x over previous
#include <cuda_runtime.h>
#include <cuda_bf16.h>
#include <cstdint>

#define BB 8
#define HH 8
#define NN 16384
#define KSLOT 64
#define NSPL 16            // CTA splits per batch; partial splits = 32 (x2 for hf halves)
#define CH 128
#define NITER 64
#define MLPR 4
#define QSCALE 0.18033688011112042f   // 0.125 * log2(e)

__device__ __nv_bfloat16 g_hits[(size_t)BB * NN * 256];
__device__ __nv_bfloat16 g_Wkvt[1024 * 256];
__device__ __nv_bfloat16 g_q[(size_t)BB * HH * 64 * 64];
__device__ float g_pm[BB * HH * 32 * 64];
__device__ float g_pl[BB * HH * 32 * 64];
__device__ float g_po[(size_t)BB * HH * 32 * 64 * 64];

struct __align__(16) FS {
    __nv_bfloat16 Hs[128 * 264];     // 67584
    __nv_bfloat16 Wks[64 * 264];     // 33792
    __nv_bfloat16 Wvs[64 * 264];     // 33792
    __nv_bfloat16 Ks[128 * 72];      // 18432
    __nv_bfloat16 Vs[128 * 72];      // 18432
};                                    // 172032 B

__device__ __forceinline__ uint32_t smaddr(const void* p) {
    return (uint32_t)__cvta_generic_to_shared(p);
}
__device__ __forceinline__ void ldsm4(uint32_t* r, const void* p) {
    uint32_t a = smaddr(p);
    asm volatile("ldmatrix.sync.aligned.m8n8.x4.shared.b16 {%0,%1,%2,%3},[%4];"
                 : "=r"(r[0]), "=r"(r[1]), "=r"(r[2]), "=r"(r[3]) : "r"(a));
}
__device__ __forceinline__ void ldsm4t(uint32_t* r, const void* p) {
    uint32_t a = smaddr(p);
    asm volatile("ldmatrix.sync.aligned.m8n8.x4.trans.shared.b16 {%0,%1,%2,%3},[%4];"
                 : "=r"(r[0]), "=r"(r[1]), "=r"(r[2]), "=r"(r[3]) : "r"(a));
}
__device__ __forceinline__ void mma16816(float* c, const uint32_t* a, uint32_t b0, uint32_t b1) {
    asm volatile("mma.sync.aligned.m16n8k16.row.col.f32.bf16.bf16.f32 "
                 "{%0,%1,%2,%3},{%4,%5,%6,%7},{%8,%9},{%0,%1,%2,%3};"
                 : "+f"(c[0]), "+f"(c[1]), "+f"(c[2]), "+f"(c[3])
                 : "r"(a[0]), "r"(a[1]), "r"(a[2]), "r"(a[3]), "r"(b0), "r"(b1));
}
__device__ __forceinline__ void cpasync16(void* dst, const void* src) {
    uint32_t d = smaddr(dst);
    asm volatile("cp.async.ca.shared.global [%0],[%1],16;" :: "r"(d), "l"(src) : "memory");
}
__device__ __forceinline__ void cpcommit() { asm volatile("cp.async.commit_group;" ::: "memory"); }
__device__ __forceinline__ void cpwait0()  { asm volatile("cp.async.wait_group 0;" ::: "memory"); }
__device__ __forceinline__ uint32_t packbf(float a, float b) {
    __nv_bfloat162 t = __floats2bfloat162_rn(a, b);
    return *reinterpret_cast<uint32_t*>(&t);
}

// ================= prep: cvt_hits + prep_w + ln1_q in ONE launch =================
__global__ void __launch_bounds__(256) prep_all(const float4* __restrict__ hits4,
                                                const float* __restrict__ Wk,
                                                const float* __restrict__ Wv,
                                                const float* __restrict__ slots,
                                                const float* __restrict__ g1,
                                                const float* __restrict__ be1,
                                                const float* __restrict__ Wq) {
    __shared__ float xs[8][256];
    int bid = blockIdx.x, t = threadIdx.x;
    if (bid < 8192) {                        // cvt hits: 2M float4, one per thread
        int i = bid * 256 + t;
        float4 v = hits4[i];
        __nv_bfloat162* out = reinterpret_cast<__nv_bfloat162*>(g_hits);
        out[2 * i]     = __floats2bfloat162_rn(v.x, v.y);
        out[2 * i + 1] = __floats2bfloat162_rn(v.z, v.w);
        return;
    }
    if (bid < 9216) {                        // prep_w
        int i = (bid - 8192) * 256 + t;
        int j = i >> 8, kk = i & 255;
        float v = (j < 512) ? Wk[kk * 512 + j] : Wv[kk * 512 + (j - 512)];
        g_Wkvt[i] = __float2bfloat16(v);
        return;
    }
    // ln1_q: 64 blocks, 8 rows each
    int lane = t & 31, w = t >> 5;
    int r0 = (bid - 9216) * 8;
    {
        int row = r0 + w;
        float v[8];
        float sum = 0.f;
#pragma unroll
        for (int i = 0; i < 8; i++) { v[i] = slots[(size_t)row * 256 + lane + 32 * i]; sum += v[i]; }
#pragma unroll
        for (int off = 16; off; off >>= 1) sum += __shfl_xor_sync(0xffffffffu, sum, off);
        float mean = sum * (1.f / 256.f);
        float vs = 0.f;
#pragma unroll
        for (int i = 0; i < 8; i++) { float d = v[i] - mean; vs += d * d; }
#pragma unroll
        for (int off = 16; off; off >>= 1) vs += __shfl_xor_sync(0xffffffffu, vs, off);
        float inv = rsqrtf(vs * (1.f / 256.f) + 1e-5f);
#pragma unroll
        for (int i = 0; i < 8; i++) {
            int c = lane + 32 * i;
            xs[w][c] = (v[i] - mean) * inv * g1[c] + be1[c];
        }
    }
    __syncthreads();
    float acc0[8] = {}, acc1[8] = {};
    for (int kk = 0; kk < 256; kk++) {
        float w0 = Wq[kk * 512 + t];
        float w1 = Wq[kk * 512 + t + 256];
#pragma unroll
        for (int r = 0; r < 8; r++) {
            float x = xs[r][kk];
            acc0[r] += x * w0; acc1[r] += x * w1;
        }
    }
#pragma unroll
    for (int r = 0; r < 8; r++) {
        int row = r0 + r, b = row >> 6, k = row & 63;
        int h0 = t >> 6, d0 = t & 63;
        g_q[(((size_t)b * HH + h0) * 64 + k) * 64 + d0] = __float2bfloat16(acc0[r] * QSCALE);
        int j1 = t + 256, h1 = j1 >> 6, d1 = j1 & 63;
        g_q[(((size_t)b * HH + h1) * 64 + k) * 64 + d1] = __float2bfloat16(acc1[r] * QSCALE);
    }
}

// ================= fused KV-projection + flash attention (3 barriers/chunk) ======
__global__ void __launch_bounds__(256, 1) fused_attn() {
    extern __shared__ char smraw[];
    FS& sm = *reinterpret_cast<FS*>(smraw);

    const int s = blockIdx.x, b = blockIdx.y;
    const int tid = threadIdx.x, lane = tid & 31, warp = tid >> 5;
    const int wm = (warp >> 1) * 32, wn = (warp & 1) * 32;  // projection tiling
    const int p = warp & 3, hf = warp >> 2;                  // attention tiling
    const int g = lane >> 2, t4 = lane & 3;
    const size_t cta_row0 = (size_t)b * NN + (size_t)s * (NN / NSPL);

    auto issueH = [&](int c) {
        const __nv_bfloat16* src = g_hits + (cta_row0 + (size_t)c * CH) * 256;
#pragma unroll
        for (int i = 0; i < 16; i++) {
            int idx = tid + 256 * i;            // 0..4095
            int row = idx >> 5, seg = (idx & 31) * 8;
            cpasync16(sm.Hs + row * 264 + seg, src + (size_t)row * 256 + seg);
        }
        cpcommit();
    };
    auto issueW = [&](int h) {
#pragma unroll
        for (int i = 0; i < 8; i++) {
            int idx = tid + 256 * i;            // 0..2047
            int row = idx >> 5, seg = (idx & 31) * 8;
            cpasync16(sm.Wks + row * 264 + seg, g_Wkvt + (size_t)(h * 64 + row) * 256 + seg);
            cpasync16(sm.Wvs + row * 264 + seg, g_Wkvt + (size_t)(512 + h * 64 + row) * 256 + seg);
        }
        cpcommit();
    };

    issueW(0);
    issueH(0);

    float mrow[2], lrow[2], oacc[8][4];
    uint32_t qa[4][4];

    for (int i = 0; i < NITER; i++) {
        const int h = i >> 3, c = i & 7;
        const int bh = b * HH + h;

        cpwait0();
        __syncthreads();                         // (1) H/W ready; prev attn done

        // -------- projection: [K|V][128x64] = H[128x256] @ W^T --------
        float kacc[2][4][4] = {}, vacc[2][4][4] = {};
#pragma unroll
        for (int ks = 0; ks < 16; ks++) {
            uint32_t af[2][4];
#pragma unroll
            for (int mi = 0; mi < 2; mi++)
                ldsm4(af[mi], sm.Hs + (wm + mi * 16 + (lane & 15)) * 264 + ks * 16 + (lane >> 4) * 8);
#pragma unroll
            for (int nb = 0; nb < 2; nb++) {
                int nrow = wn + nb * 16 + (lane & 7) + ((lane >> 4) << 3);
                uint32_t bf[4], cf[4];
                ldsm4(bf, sm.Wks + nrow * 264 + ks * 16 + (lane & 8));
                mma16816(kacc[0][2 * nb],     af[0], bf[0], bf[1]);
                mma16816(kacc[0][2 * nb + 1], af[0], bf[2], bf[3]);
                mma16816(kacc[1][2 * nb],     af[1], bf[0], bf[1]);
                mma16816(kacc[1][2 * nb + 1], af[1], bf[2], bf[3]);
                ldsm4(cf, sm.Wvs + nrow * 264 + ks * 16 + (lane & 8));
                mma16816(vacc[0][2 * nb],     af[0], cf[0], cf[1]);
                mma16816(vacc[0][2 * nb + 1], af[0], cf[2], cf[3]);
                mma16816(vacc[1][2 * nb],     af[1], cf[0], cf[1]);
                mma16816(vacc[1][2 * nb + 1], af[1], cf[2], cf[3]);
            }
        }
        __syncthreads();                         // (2) Hs/Ws reads complete

        if (i + 1 < NITER) {
            if (c == 7) issueW(h + 1);
            issueH((c == 7) ? 0 : c + 1);
        }

        // epilogue -> bf16 K/V smem tiles
#pragma unroll
        for (int mi = 0; mi < 2; mi++) {
            int row = wm + mi * 16 + g;
#pragma unroll
            for (int nj = 0; nj < 4; nj++) {
                int col = wn + nj * 8 + 2 * t4;
                *(uint32_t*)&sm.Ks[row * 72 + col]       = packbf(kacc[mi][nj][0], kacc[mi][nj][1]);
                *(uint32_t*)&sm.Ks[(row + 8) * 72 + col] = packbf(kacc[mi][nj][2], kacc[mi][nj][3]);
                *(uint32_t*)&sm.Vs[row * 72 + col]       = packbf(vacc[mi][nj][0], vacc[mi][nj][1]);
                *(uint32_t*)&sm.Vs[(row + 8) * 72 + col] = packbf(vacc[mi][nj][2], vacc[mi][nj][3]);
            }
        }

        if (c == 0) {                            // Q frags direct from gmem; reset state
            const uint32_t* qp = (const uint32_t*)(g_q + (size_t)bh * 4096);
            int rq = p * 16 + g;
#pragma unroll
            for (int ks = 0; ks < 4; ks++) {
                int cb = ks * 16 + t4 * 2;
                qa[ks][0] = qp[(rq * 64 + cb) >> 1];
                qa[ks][1] = qp[((rq + 8) * 64 + cb) >> 1];
                qa[ks][2] = qp[(rq * 64 + cb + 8) >> 1];
                qa[ks][3] = qp[((rq + 8) * 64 + cb + 8) >> 1];
            }
            mrow[0] = mrow[1] = -1e30f;
            lrow[0] = lrow[1] = 0.f;
#pragma unroll
            for (int dt = 0; dt < 8; dt++)
#pragma unroll
                for (int r = 0; r < 4; r++) oacc[dt][r] = 0.f;
        }
        __syncthreads();                         // (3) K/V tiles visible

        // -------- attention: QK^T over this warp's n-half --------
        float sacc[8][4] = {};
#pragma unroll
        for (int ks = 0; ks < 4; ks++) {
#pragma unroll
            for (int np = 0; np < 4; np++) {
                int nrow = hf * 64 + np * 16 + (lane & 7) + ((lane >> 4) << 3);
                uint32_t bf[4];
                ldsm4(bf, sm.Ks + nrow * 72 + ks * 16 + (lane & 8));
                mma16816(sacc[2 * np],     qa[ks], bf[0], bf[1]);
                mma16816(sacc[2 * np + 1], qa[ks], bf[2], bf[3]);
            }
        }
        // -------- independent in-warp online softmax (log2 domain) --------
#pragma unroll
        for (int r = 0; r < 2; r++) {
            float m = -1e30f;
#pragma unroll
            for (int nt = 0; nt < 8; nt++)
                m = fmaxf(m, fmaxf(sacc[nt][2 * r], sacc[nt][2 * r + 1]));
            m = fmaxf(m, __shfl_xor_sync(0xffffffffu, m, 1));
            m = fmaxf(m, __shfl_xor_sync(0xffffffffu, m, 2));
            float mnew = fmaxf(mrow[r], m);
            float sc = exp2f(mrow[r] - mnew);
            mrow[r] = mnew;
            float sum = 0.f;
#pragma unroll
            for (int nt = 0; nt < 8; nt++) {
                float p0 = exp2f(sacc[nt][2 * r] - mnew);
                float p1 = exp2f(sacc[nt][2 * r + 1] - mnew);
                sacc[nt][2 * r] = p0; sacc[nt][2 * r + 1] = p1;
                sum += p0 + p1;
            }
            sum += __shfl_xor_sync(0xffffffffu, sum, 1);
            sum += __shfl_xor_sync(0xffffffffu, sum, 2);
            lrow[r] = lrow[r] * sc + sum;
#pragma unroll
            for (int dt = 0; dt < 8; dt++) {
                oacc[dt][2 * r] *= sc; oacc[dt][2 * r + 1] *= sc;
            }
        }
        // -------- P @ V over this n-half --------
        uint32_t pf[4][4];
#pragma unroll
        for (int k2 = 0; k2 < 4; k2++) {
            pf[k2][0] = packbf(sacc[2 * k2][0],     sacc[2 * k2][1]);
            pf[k2][1] = packbf(sacc[2 * k2][2],     sacc[2 * k2][3]);
            pf[k2][2] = packbf(sacc[2 * k2 + 1][0], sacc[2 * k2 + 1][1]);
            pf[k2][3] = packbf(sacc[2 * k2 + 1][2], sacc[2 * k2 + 1][3]);
        }
#pragma unroll
        for (int k2 = 0; k2 < 4; k2++) {
#pragma unroll
            for (int dp = 0; dp < 4; dp++) {
                uint32_t vf[4];
                ldsm4t(vf, sm.Vs + (hf * 64 + k2 * 16 + (lane & 15)) * 72
                            + dp * 16 + (lane >> 4) * 8);
                mma16816(oacc[2 * dp],     pf[k2], vf[0], vf[1]);
                mma16816(oacc[2 * dp + 1], pf[k2], vf[2], vf[3]);
            }
        }

        // -------- head end: each hf half writes its OWN split partial --------
        if (c == 7) {
            const int base = (bh * 32 + hf * 16 + s) * 64;
            const int r0 = p * 16 + g;
#pragma unroll
            for (int dt = 0; dt < 8; dt++) {
                int col = dt * 8 + 2 * t4;
                *(float2*)&g_po[(size_t)(base + r0) * 64 + col] =
                    make_float2(oacc[dt][0], oacc[dt][1]);
                *(float2*)&g_po[(size_t)(base + r0 + 8) * 64 + col] =
                    make_float2(oacc[dt][2], oacc[dt][3]);
            }
            if (t4 == 0) {
                g_pm[base + r0] = mrow[0]; g_pm[base + r0 + 8] = mrow[1];
                g_pl[base + r0] = lrow[0]; g_pl[base + r0 + 8] = lrow[1];
            }
        }
    }
}

// ================= combine(32 splits) + MLP + residual + LN2 =====================
__global__ void __launch_bounds__(256) mlp_ln2(const float* __restrict__ slots,
                                               const float* __restrict__ W1,
                                               const float* __restrict__ b1,
                                               const float* __restrict__ W2,
                                               const float* __restrict__ b2,
                                               const float* __restrict__ g2,
                                               const float* __restrict__ be2,
                                               float* __restrict__ out) {
    __shared__ float av[MLPR][512];
    __shared__ float hid[MLPR][512];
    __shared__ float red[256];
    int t = threadIdx.x;
    int r0 = blockIdx.x * MLPR;
#pragma unroll
    for (int r = 0; r < MLPR; r++) {
        int row = r0 + r, bB = row >> 6, kk = row & 63;
#pragma unroll
        for (int jj = 0; jj < 2; jj++) {
            int d = t + 256 * jj;
            int h = d >> 6, dd = d & 63;
            int bh = bB * 8 + h;
            float M = -1e30f;
#pragma unroll
            for (int ss = 0; ss < 32; ss++)
                M = fmaxf(M, g_pm[(bh * 32 + ss) * 64 + kk]);
            float L = 0.f, acc = 0.f;
#pragma unroll
            for (int ss = 0; ss < 32; ss++) {
                int idx = (bh * 32 + ss) * 64 + kk;
                float w = exp2f(g_pm[idx] - M);
                L   += g_pl[idx] * w;
                acc += g_po[(size_t)idx * 64 + dd] * w;
            }
            av[r][d] = acc / L;
        }
    }
    __syncthreads();
    float a0[MLPR], a1[MLPR];
    float bb0 = b1[t], bb1 = b1[t + 256];
#pragma unroll
    for (int r = 0; r < MLPR; r++) { a0[r] = bb0; a1[r] = bb1; }
    for (int kk = 0; kk < 512; kk++) {
        float w0 = W1[kk * 512 + t];
        float w1 = W1[kk * 512 + t + 256];
#pragma unroll
        for (int r = 0; r < MLPR; r++) {
            float x = av[r][kk];
            a0[r] += x * w0; a1[r] += x * w1;
        }
    }
#pragma unroll
    for (int r = 0; r < MLPR; r++) {
        hid[r][t] = fmaxf(a0[r], 0.f);
        hid[r][t + 256] = fmaxf(a1[r], 0.f);
    }
    __syncthreads();
    float o[MLPR];
    float c0 = b2[t];
#pragma unroll
    for (int r = 0; r < MLPR; r++) o[r] = c0;
    for (int kk = 0; kk < 512; kk++) {
        float w = W2[kk * 256 + t];
#pragma unroll
        for (int r = 0; r < MLPR; r++) o[r] += hid[r][kk] * w;
    }
    float gg = g2[t], bbn = be2[t];
    for (int r = 0; r < MLPR; r++) {
        float x = slots[(size_t)(r0 + r) * 256 + t] + o[r];
        red[t] = x; __syncthreads();
        for (int off = 128; off; off >>= 1) { if (t < off) red[t] += red[t + off]; __syncthreads(); }
        float mean = red[0] * (1.f / 256.f); __syncthreads();
        float d = x - mean;
        red[t] = d * d; __syncthreads();
        for (int off = 128; off; off >>= 1) { if (t < off) red[t] += red[t + off]; __syncthreads(); }
        float var = red[0] * (1.f / 256.f); __syncthreads();
        out[(size_t)(r0 + r) * 256 + t] = d * rsqrtf(var + 1e-5f) * gg + bbn;
    }
}

extern "C" void kernel_launch(void* const* d_in, const int* in_sizes, int n_in,
                              void* d_out, int out_size) {
    const float* slots = (const float*)d_in[0];
    const float* hits  = (const float*)d_in[1];
    const float* ln1g  = (const float*)d_in[2];
    const float* ln1b  = (const float*)d_in[3];
    const float* Wq    = (const float*)d_in[4];
    const float* Wk    = (const float*)d_in[5];
    const float* Wv    = (const float*)d_in[6];
    const float* W1    = (const float*)d_in[7];
    const float* b1    = (const float*)d_in[8];
    const float* W2    = (const float*)d_in[9];
    const float* b2    = (const float*)d_in[10];
    const float* ln2g  = (const float*)d_in[11];
    const float* ln2b  = (const float*)d_in[12];
    float* out = (float*)d_out;

    cudaFuncSetAttribute(fused_attn, cudaFuncAttributeMaxDynamicSharedMemorySize,
                         (int)sizeof(FS));
    prep_all<<<9280, 256>>>((const float4*)hits, Wk, Wv, slots, ln1g, ln1b, Wq);
    fused_attn<<<dim3(NSPL, BB), 256, sizeof(FS)>>>();
    mlp_ln2<<<BB * KSLOT / MLPR, 256>>>(slots, W1, b1, W2, b2, ln2g, ln2b, out);
}

// round 9
// speedup vs baseline: 1.3515x; 1.0319x over previous
#include <cuda_runtime.h>
#include <cuda_bf16.h>
#include <cstdint>

#define BB 8
#define HH 8
#define NN 16384
#define KSLOT 64
#define NSPL 16
#define CH 128
#define NITER 64
#define MLPR 4
#define QSCALE 0.18033688011112042f   // 0.125 * log2(e)

__device__ __nv_bfloat16 g_hits[(size_t)BB * NN * 256];
__device__ __nv_bfloat16 g_Wkvt[1024 * 256];
__device__ __nv_bfloat16 g_q[(size_t)BB * HH * 64 * 64];
__device__ float g_pm[BB * HH * 32 * 64];
__device__ float g_pl[BB * HH * 32 * 64];
__device__ float g_po[(size_t)BB * HH * 32 * 64 * 64];

struct __align__(16) FS {
    __nv_bfloat16 Hs[128 * 264];     // 67584
    __nv_bfloat16 Wks[64 * 264];     // 33792
    __nv_bfloat16 Wvs[64 * 264];     // 33792
    __nv_bfloat16 Ks[128 * 72];      // 18432
    __nv_bfloat16 Vs[128 * 72];      // 18432
};                                    // 172032 B

__device__ __forceinline__ uint32_t smaddr(const void* p) {
    return (uint32_t)__cvta_generic_to_shared(p);
}
__device__ __forceinline__ void ldsm4(uint32_t* r, const void* p) {
    uint32_t a = smaddr(p);
    asm volatile("ldmatrix.sync.aligned.m8n8.x4.shared.b16 {%0,%1,%2,%3},[%4];"
                 : "=r"(r[0]), "=r"(r[1]), "=r"(r[2]), "=r"(r[3]) : "r"(a));
}
__device__ __forceinline__ void ldsm4t(uint32_t* r, const void* p) {
    uint32_t a = smaddr(p);
    asm volatile("ldmatrix.sync.aligned.m8n8.x4.trans.shared.b16 {%0,%1,%2,%3},[%4];"
                 : "=r"(r[0]), "=r"(r[1]), "=r"(r[2]), "=r"(r[3]) : "r"(a));
}
__device__ __forceinline__ void mma16816(float* c, const uint32_t* a, uint32_t b0, uint32_t b1) {
    asm volatile("mma.sync.aligned.m16n8k16.row.col.f32.bf16.bf16.f32 "
                 "{%0,%1,%2,%3},{%4,%5,%6,%7},{%8,%9},{%0,%1,%2,%3};"
                 : "+f"(c[0]), "+f"(c[1]), "+f"(c[2]), "+f"(c[3])
                 : "r"(a[0]), "r"(a[1]), "r"(a[2]), "r"(a[3]), "r"(b0), "r"(b1));
}
__device__ __forceinline__ void cpasync16(void* dst, const void* src) {
    uint32_t d = smaddr(dst);
    asm volatile("cp.async.ca.shared.global [%0],[%1],16;" :: "r"(d), "l"(src) : "memory");
}
__device__ __forceinline__ void cpcommit() { asm volatile("cp.async.commit_group;" ::: "memory"); }
__device__ __forceinline__ void cpwait0()  { asm volatile("cp.async.wait_group 0;" ::: "memory"); }
__device__ __forceinline__ uint32_t packbf(float a, float b) {
    __nv_bfloat162 t = __floats2bfloat162_rn(a, b);
    return *reinterpret_cast<uint32_t*>(&t);
}

// ================= prep: cvt_hits(ILP4) + prep_w(ILP4) + ln1_q, one launch =======
__global__ void __launch_bounds__(256) prep_all(const float4* __restrict__ hits4,
                                                const float* __restrict__ Wk,
                                                const float* __restrict__ Wv,
                                                const float* __restrict__ slots,
                                                const float* __restrict__ g1,
                                                const float* __restrict__ be1,
                                                const float* __restrict__ Wq) {
    __shared__ float xs[8][256];
    int bid = blockIdx.x, t = threadIdx.x;
    if (bid < 2048) {                        // cvt hits: 4 consecutive float4/thread
        int base = (bid * 256 + t) * 4;
        float4 v0 = hits4[base], v1 = hits4[base + 1], v2 = hits4[base + 2], v3 = hits4[base + 3];
        __nv_bfloat162* out = reinterpret_cast<__nv_bfloat162*>(g_hits);
        out[2 * base]     = __floats2bfloat162_rn(v0.x, v0.y);
        out[2 * base + 1] = __floats2bfloat162_rn(v0.z, v0.w);
        out[2 * base + 2] = __floats2bfloat162_rn(v1.x, v1.y);
        out[2 * base + 3] = __floats2bfloat162_rn(v1.z, v1.w);
        out[2 * base + 4] = __floats2bfloat162_rn(v2.x, v2.y);
        out[2 * base + 5] = __floats2bfloat162_rn(v2.z, v2.w);
        out[2 * base + 6] = __floats2bfloat162_rn(v3.x, v3.y);
        out[2 * base + 7] = __floats2bfloat162_rn(v3.z, v3.w);
        return;
    }
    if (bid < 2304) {                        // prep_w: 4 elems/thread (consecutive k)
        int i0 = ((bid - 2048) * 256 + t) * 4;
        int j = i0 >> 8, kk = i0 & 255;
        float v0, v1, v2, v3;
        if (j < 512) {
            v0 = Wk[(kk + 0) * 512 + j]; v1 = Wk[(kk + 1) * 512 + j];
            v2 = Wk[(kk + 2) * 512 + j]; v3 = Wk[(kk + 3) * 512 + j];
        } else {
            int jj = j - 512;
            v0 = Wv[(kk + 0) * 512 + jj]; v1 = Wv[(kk + 1) * 512 + jj];
            v2 = Wv[(kk + 2) * 512 + jj]; v3 = Wv[(kk + 3) * 512 + jj];
        }
        __nv_bfloat162* dst = reinterpret_cast<__nv_bfloat162*>(g_Wkvt + i0);
        dst[0] = __floats2bfloat162_rn(v0, v1);
        dst[1] = __floats2bfloat162_rn(v2, v3);
        return;
    }
    // ln1_q: 64 blocks, 8 rows each
    int lane = t & 31, w = t >> 5;
    int r0 = (bid - 2304) * 8;
    {
        int row = r0 + w;
        float v[8];
        float sum = 0.f;
#pragma unroll
        for (int i = 0; i < 8; i++) { v[i] = slots[(size_t)row * 256 + lane + 32 * i]; sum += v[i]; }
#pragma unroll
        for (int off = 16; off; off >>= 1) sum += __shfl_xor_sync(0xffffffffu, sum, off);
        float mean = sum * (1.f / 256.f);
        float vs = 0.f;
#pragma unroll
        for (int i = 0; i < 8; i++) { float d = v[i] - mean; vs += d * d; }
#pragma unroll
        for (int off = 16; off; off >>= 1) vs += __shfl_xor_sync(0xffffffffu, vs, off);
        float inv = rsqrtf(vs * (1.f / 256.f) + 1e-5f);
#pragma unroll
        for (int i = 0; i < 8; i++) {
            int c = lane + 32 * i;
            xs[w][c] = (v[i] - mean) * inv * g1[c] + be1[c];
        }
    }
    __syncthreads();
    float acc0[8] = {}, acc1[8] = {};
    for (int kk = 0; kk < 256; kk++) {
        float w0 = Wq[kk * 512 + t];
        float w1 = Wq[kk * 512 + t + 256];
#pragma unroll
        for (int r = 0; r < 8; r++) {
            float x = xs[r][kk];
            acc0[r] += x * w0; acc1[r] += x * w1;
        }
    }
#pragma unroll
    for (int r = 0; r < 8; r++) {
        int row = r0 + r, b = row >> 6, k = row & 63;
        int h0 = t >> 6, d0 = t & 63;
        g_q[(((size_t)b * HH + h0) * 64 + k) * 64 + d0] = __float2bfloat16(acc0[r] * QSCALE);
        int j1 = t + 256, h1 = j1 >> 6, d1 = j1 & 63;
        g_q[(((size_t)b * HH + h1) * 64 + k) * 64 + d1] = __float2bfloat16(acc1[r] * QSCALE);
    }
}

// ================= fused KV-projection + flash attention (2 barriers/chunk) ======
__global__ void __launch_bounds__(256, 1) fused_attn() {
    extern __shared__ char smraw[];
    FS& sm = *reinterpret_cast<FS*>(smraw);

    const int s = blockIdx.x, b = blockIdx.y;
    const int tid = threadIdx.x, lane = tid & 31, warp = tid >> 5;
    const int wm = (warp >> 1) * 32, wn = (warp & 1) * 32;  // projection tiling
    const int p = warp & 3, hf = warp >> 2;                  // attention tiling
    const int g = lane >> 2, t4 = lane & 3;
    const size_t cta_row0 = (size_t)b * NN + (size_t)s * (NN / NSPL);

    auto issueH = [&](int c) {
        const __nv_bfloat16* src = g_hits + (cta_row0 + (size_t)c * CH) * 256;
#pragma unroll
        for (int i = 0; i < 16; i++) {
            int idx = tid + 256 * i;
            int row = idx >> 5, seg = (idx & 31) * 8;
            cpasync16(sm.Hs + row * 264 + seg, src + (size_t)row * 256 + seg);
        }
        cpcommit();
    };
    auto issueW = [&](int h) {
#pragma unroll
        for (int i = 0; i < 8; i++) {
            int idx = tid + 256 * i;
            int row = idx >> 5, seg = (idx & 31) * 8;
            cpasync16(sm.Wks + row * 264 + seg, g_Wkvt + (size_t)(h * 64 + row) * 256 + seg);
            cpasync16(sm.Wvs + row * 264 + seg, g_Wkvt + (size_t)(512 + h * 64 + row) * 256 + seg);
        }
        cpcommit();
    };

    issueW(0);
    issueH(0);

    float mrow[2], lrow[2], oacc[8][4];
    uint32_t qa[4][4];

    for (int i = 0; i < NITER; i++) {
        const int h = i >> 3, c = i & 7;
        const int bh = b * HH + h;

        cpwait0();
        __syncthreads();                         // (1) H/W ready; prev attn done with KV

        // -------- projection: [K|V][128x64] = H[128x256] @ W^T --------
        float kacc[2][4][4] = {}, vacc[2][4][4] = {};
#pragma unroll
        for (int ks = 0; ks < 16; ks++) {
            uint32_t af[2][4];
#pragma unroll
            for (int mi = 0; mi < 2; mi++)
                ldsm4(af[mi], sm.Hs + (wm + mi * 16 + (lane & 15)) * 264 + ks * 16 + (lane >> 4) * 8);
#pragma unroll
            for (int nb = 0; nb < 2; nb++) {
                int nrow = wn + nb * 16 + (lane & 7) + ((lane >> 4) << 3);
                uint32_t bf[4], cf[4];
                ldsm4(bf, sm.Wks + nrow * 264 + ks * 16 + (lane & 8));
                mma16816(kacc[0][2 * nb],     af[0], bf[0], bf[1]);
                mma16816(kacc[0][2 * nb + 1], af[0], bf[2], bf[3]);
                mma16816(kacc[1][2 * nb],     af[1], bf[0], bf[1]);
                mma16816(kacc[1][2 * nb + 1], af[1], bf[2], bf[3]);
                ldsm4(cf, sm.Wvs + nrow * 264 + ks * 16 + (lane & 8));
                mma16816(vacc[0][2 * nb],     af[0], cf[0], cf[1]);
                mma16816(vacc[0][2 * nb + 1], af[0], cf[2], cf[3]);
                mma16816(vacc[1][2 * nb],     af[1], cf[0], cf[1]);
                mma16816(vacc[1][2 * nb + 1], af[1], cf[2], cf[3]);
            }
        }

        // epilogue -> bf16 K/V smem tiles (safe: prev attn reads done at bar 1)
#pragma unroll
        for (int mi = 0; mi < 2; mi++) {
            int row = wm + mi * 16 + g;
#pragma unroll
            for (int nj = 0; nj < 4; nj++) {
                int col = wn + nj * 8 + 2 * t4;
                *(uint32_t*)&sm.Ks[row * 72 + col]       = packbf(kacc[mi][nj][0], kacc[mi][nj][1]);
                *(uint32_t*)&sm.Ks[(row + 8) * 72 + col] = packbf(kacc[mi][nj][2], kacc[mi][nj][3]);
                *(uint32_t*)&sm.Vs[row * 72 + col]       = packbf(vacc[mi][nj][0], vacc[mi][nj][1]);
                *(uint32_t*)&sm.Vs[(row + 8) * 72 + col] = packbf(vacc[mi][nj][2], vacc[mi][nj][3]);
            }
        }
        __syncthreads();                         // (2) proj reads done + KV visible

        if (i + 1 < NITER) {                     // overlaps attention below
            if (c == 7) issueW(h + 1);
            issueH((c == 7) ? 0 : c + 1);
        }

        if (c == 0) {                            // Q frags direct from gmem; reset state
            const uint32_t* qp = (const uint32_t*)(g_q + (size_t)bh * 4096);
            int rq = p * 16 + g;
#pragma unroll
            for (int ks = 0; ks < 4; ks++) {
                int cb = ks * 16 + t4 * 2;
                qa[ks][0] = qp[(rq * 64 + cb) >> 1];
                qa[ks][1] = qp[((rq + 8) * 64 + cb) >> 1];
                qa[ks][2] = qp[(rq * 64 + cb + 8) >> 1];
                qa[ks][3] = qp[((rq + 8) * 64 + cb + 8) >> 1];
            }
            mrow[0] = mrow[1] = -1e30f;
            lrow[0] = lrow[1] = 0.f;
#pragma unroll
            for (int dt = 0; dt < 8; dt++)
#pragma unroll
                for (int r = 0; r < 4; r++) oacc[dt][r] = 0.f;
        }

        // -------- attention: QK^T over this warp's n-half --------
        float sacc[8][4] = {};
#pragma unroll
        for (int ks = 0; ks < 4; ks++) {
#pragma unroll
            for (int np = 0; np < 4; np++) {
                int nrow = hf * 64 + np * 16 + (lane & 7) + ((lane >> 4) << 3);
                uint32_t bf[4];
                ldsm4(bf, sm.Ks + nrow * 72 + ks * 16 + (lane & 8));
                mma16816(sacc[2 * np],     qa[ks], bf[0], bf[1]);
                mma16816(sacc[2 * np + 1], qa[ks], bf[2], bf[3]);
            }
        }
        // -------- independent in-warp online softmax (log2 domain) --------
#pragma unroll
        for (int r = 0; r < 2; r++) {
            float m = -1e30f;
#pragma unroll
            for (int nt = 0; nt < 8; nt++)
                m = fmaxf(m, fmaxf(sacc[nt][2 * r], sacc[nt][2 * r + 1]));
            m = fmaxf(m, __shfl_xor_sync(0xffffffffu, m, 1));
            m = fmaxf(m, __shfl_xor_sync(0xffffffffu, m, 2));
            float mnew = fmaxf(mrow[r], m);
            float sc = exp2f(mrow[r] - mnew);
            mrow[r] = mnew;
            float sum = 0.f;
#pragma unroll
            for (int nt = 0; nt < 8; nt++) {
                float p0 = exp2f(sacc[nt][2 * r] - mnew);
                float p1 = exp2f(sacc[nt][2 * r + 1] - mnew);
                sacc[nt][2 * r] = p0; sacc[nt][2 * r + 1] = p1;
                sum += p0 + p1;
            }
            sum += __shfl_xor_sync(0xffffffffu, sum, 1);
            sum += __shfl_xor_sync(0xffffffffu, sum, 2);
            lrow[r] = lrow[r] * sc + sum;
#pragma unroll
            for (int dt = 0; dt < 8; dt++) {
                oacc[dt][2 * r] *= sc; oacc[dt][2 * r + 1] *= sc;
            }
        }
        // -------- P @ V over this n-half --------
        uint32_t pf[4][4];
#pragma unroll
        for (int k2 = 0; k2 < 4; k2++) {
            pf[k2][0] = packbf(sacc[2 * k2][0],     sacc[2 * k2][1]);
            pf[k2][1] = packbf(sacc[2 * k2][2],     sacc[2 * k2][3]);
            pf[k2][2] = packbf(sacc[2 * k2 + 1][0], sacc[2 * k2 + 1][1]);
            pf[k2][3] = packbf(sacc[2 * k2 + 1][2], sacc[2 * k2 + 1][3]);
        }
#pragma unroll
        for (int k2 = 0; k2 < 4; k2++) {
#pragma unroll
            for (int dp = 0; dp < 4; dp++) {
                uint32_t vf[4];
                ldsm4t(vf, sm.Vs + (hf * 64 + k2 * 16 + (lane & 15)) * 72
                            + dp * 16 + (lane >> 4) * 8);
                mma16816(oacc[2 * dp],     pf[k2], vf[0], vf[1]);
                mma16816(oacc[2 * dp + 1], pf[k2], vf[2], vf[3]);
            }
        }

        // -------- head end: each hf half writes its OWN split partial --------
        if (c == 7) {
            const int base = (bh * 32 + hf * 16 + s) * 64;
            const int r0 = p * 16 + g;
#pragma unroll
            for (int dt = 0; dt < 8; dt++) {
                int col = dt * 8 + 2 * t4;
                *(float2*)&g_po[(size_t)(base + r0) * 64 + col] =
                    make_float2(oacc[dt][0], oacc[dt][1]);
                *(float2*)&g_po[(size_t)(base + r0 + 8) * 64 + col] =
                    make_float2(oacc[dt][2], oacc[dt][3]);
            }
            if (t4 == 0) {
                g_pm[base + r0] = mrow[0]; g_pm[base + r0 + 8] = mrow[1];
                g_pl[base + r0] = lrow[0]; g_pl[base + r0 + 8] = lrow[1];
            }
        }
    }
}

// ================= combine(32 splits) + MLP + residual + LN2 =====================
__global__ void __launch_bounds__(256) mlp_ln2(const float* __restrict__ slots,
                                               const float* __restrict__ W1,
                                               const float* __restrict__ b1,
                                               const float* __restrict__ W2,
                                               const float* __restrict__ b2,
                                               const float* __restrict__ g2,
                                               const float* __restrict__ be2,
                                               float* __restrict__ out) {
    __shared__ float av[MLPR][512];
    __shared__ float hid[MLPR][512];
    __shared__ float red[256];
    int t = threadIdx.x;
    int r0 = blockIdx.x * MLPR;
#pragma unroll
    for (int r = 0; r < MLPR; r++) {
        int row = r0 + r, bB = row >> 6, kk = row & 63;
#pragma unroll
        for (int jj = 0; jj < 2; jj++) {
            int d = t + 256 * jj;
            int h = d >> 6, dd = d & 63;
            int bh = bB * 8 + h;
            float M = -1e30f;
#pragma unroll
            for (int ss = 0; ss < 32; ss++)
                M = fmaxf(M, g_pm[(bh * 32 + ss) * 64 + kk]);
            float L = 0.f, acc = 0.f;
#pragma unroll
            for (int ss = 0; ss < 32; ss++) {
                int idx = (bh * 32 + ss) * 64 + kk;
                float w = exp2f(g_pm[idx] - M);
                L   += g_pl[idx] * w;
                acc += g_po[(size_t)idx * 64 + dd] * w;
            }
            av[r][d] = acc / L;
        }
    }
    __syncthreads();
    float a0[MLPR], a1[MLPR];
    float bb0 = b1[t], bb1 = b1[t + 256];
#pragma unroll
    for (int r = 0; r < MLPR; r++) { a0[r] = bb0; a1[r] = bb1; }
    for (int kk = 0; kk < 512; kk++) {
        float w0 = W1[kk * 512 + t];
        float w1 = W1[kk * 512 + t + 256];
#pragma unroll
        for (int r = 0; r < MLPR; r++) {
            float x = av[r][kk];
            a0[r] += x * w0; a1[r] += x * w1;
        }
    }
#pragma unroll
    for (int r = 0; r < MLPR; r++) {
        hid[r][t] = fmaxf(a0[r], 0.f);
        hid[r][t + 256] = fmaxf(a1[r], 0.f);
    }
    __syncthreads();
    float o[MLPR];
    float c0 = b2[t];
#pragma unroll
    for (int r = 0; r < MLPR; r++) o[r] = c0;
    for (int kk = 0; kk < 512; kk++) {
        float w = W2[kk * 256 + t];
#pragma unroll
        for (int r = 0; r < MLPR; r++) o[r] += hid[r][kk] * w;
    }
    float gg = g2[t], bbn = be2[t];
    for (int r = 0; r < MLPR; r++) {
        float x = slots[(size_t)(r0 + r) * 256 + t] + o[r];
        red[t] = x; __syncthreads();
        for (int off = 128; off; off >>= 1) { if (t < off) red[t] += red[t + off]; __syncthreads(); }
        float mean = red[0] * (1.f / 256.f); __syncthreads();
        float d = x - mean;
        red[t] = d * d; __syncthreads();
        for (int off = 128; off; off >>= 1) { if (t < off) red[t] += red[t + off]; __syncthreads(); }
        float var = red[0] * (1.f / 256.f); __syncthreads();
        out[(size_t)(r0 + r) * 256 + t] = d * rsqrtf(var + 1e-5f) * gg + bbn;
    }
}

extern "C" void kernel_launch(void* const* d_in, const int* in_sizes, int n_in,
                              void* d_out, int out_size) {
    const float* slots = (const float*)d_in[0];
    const float* hits  = (const float*)d_in[1];
    const float* ln1g  = (const float*)d_in[2];
    const float* ln1b  = (const float*)d_in[3];
    const float* Wq    = (const float*)d_in[4];
    const float* Wk    = (const float*)d_in[5];
    const float* Wv    = (const float*)d_in[6];
    const float* W1    = (const float*)d_in[7];
    const float* b1    = (const float*)d_in[8];
    const float* W2    = (const float*)d_in[9];
    const float* b2    = (const float*)d_in[10];
    const float* ln2g  = (const float*)d_in[11];
    const float* ln2b  = (const float*)d_in[12];
    float* out = (float*)d_out;

    cudaFuncSetAttribute(fused_attn, cudaFuncAttributeMaxDynamicSharedMemorySize,
                         (int)sizeof(FS));
    prep_all<<<2368, 256>>>((const float4*)hits, Wk, Wv, slots, ln1g, ln1b, Wq);
    fused_attn<<<dim3(NSPL, BB), 256, sizeof(FS)>>>();
    mlp_ln2<<<BB * KSLOT / MLPR, 256>>>(slots, W1, b1, W2, b2, ln2g, ln2b, out);
}